// round 10
// baseline (speedup 1.0000x reference)
#include <cuda_runtime.h>
#include <cuda_bf16.h>

// Balloon-Windkessel BOLD, explicit Euler, T=1000 steps, B=16384 sims.
// R10 = R9 arithmetic (bit-identical; rel_err 1.14e-4) + two launch/memory
// changes targeting the op-count-invariant ~90 cyc/step stall floor:
//  1. grid padded 128 -> 160 blocks (empties exit immediately): B300 has a
//     documented low-grid issue throttle (+28%) that VANISHES @grid>=148
//     (pSmIssueThrottleCtrl). Workers still get 128 distinct SMs in wave 1.
//  2. streaming cache hints: noise read once (__ldcs), output written once
//     (__stcs) -> evict-first policy, identical values.
// Evidence basis: R7->R9 cut FMA ops 23->17 with ~0% duration change, so the
// kernel is stall-bound by something structural, not by pipe throughput.

#define DT_C        0.01f
#define V0_C        0.02f
#define NOISE_AMP_C 0.01f
#define BATCH_C     16384

__device__ __forceinline__ float fast_rcp(float x) {
    float r; asm("rcp.approx.f32 %0, %1;" : "=f"(r) : "f"(x)); return r;
}

struct BWState {
    float s, f, v, q;
    float G;    // G(f) for current f (staged)
    float in1;  // fma(-mu, f-1, -sigma*s)   (staged)
    float fv;   // f - v                      (staged)
    float qd;   // G - q                      (staged)
};

struct BWConst {
    float sigma, mu, c_vl;
    float C0, C1, C2, C3;        // readout constants
    float g0, g1, g2, g3, g4;    // G(u) Taylor coefficients (deg 4)
};

// One Euler step. Carried arithmetic bit-identical to R9.
__device__ __forceinline__ float bw_step(BWState& st, const BWConst& C, float z)
{
    const float s2 = fmaf(DT_C, fmaf(NOISE_AMP_C, z, st.in1), st.s);
    const float f2 = fmaf(DT_C, st.s, st.f);
    const float v2 = fmaf(C.c_vl, st.fv, st.v);
    const float q2 = fmaf(C.c_vl, st.qd, st.q);

    // Staging for the NEXT step (pure functions of s2,f2,v2,q2):
    const float u = f2 - 1.0f;
    float p = fmaf(C.g4, u, C.g3);
    p       = fmaf(p,   u, C.g2);
    p       = fmaf(p,   u, C.g1);
    const float G = fmaf(p, u, C.g0);
    st.G   = G;
    st.in1 = fmaf(-C.mu, u, -C.sigma * s2);
    st.fv  = f2 - v2;
    st.qd  = G - q2;

    // Readout: y = C0 - C1*q2 - C3*v2 - (C2*q2)*rcp(v2)
    const float rv = fast_rcp(v2);
    const float t0 = fmaf(-C.C3, v2, C.C0);
    const float t1 = fmaf(-C.C1, q2, t0);
    const float y  = fmaf(-C.C2 * q2, rv, t1);

    st.s = s2; st.f = f2; st.v = v2; st.q = q2;
    return y;
}

template<int U, int BS>
__global__ __launch_bounds__(128, 1)
void bw_bold_kernel(const float* __restrict__ noise,
                    const float* __restrict__ sigma_p,
                    const float* __restrict__ mu_p,
                    const float* __restrict__ lamb_p,
                    const float* __restrict__ beta_p,
                    const float* __restrict__ psi_p,
                    const float* __restrict__ phi_p,
                    const float* __restrict__ chi_p,
                    float* __restrict__ out,
                    int T)
{
    const int gid = blockIdx.x * blockDim.x + threadIdx.x;
    if (gid >= BS) return;   // grid is padded past 148 blocks; empties exit

    BWConst C;
    C.sigma = __ldg(sigma_p);
    C.mu    = __ldg(mu_p);
    const float lamb = __ldg(lamb_p);
    const float beta = __ldg(beta_p);
    const float psi  = __ldg(psi_p);
    const float phi  = __ldg(phi_p);
    const float chi  = __ldg(chi_p);
    C.c_vl  = DT_C / lamb;
    C.C0    = V0_C * (phi + psi + chi);
    C.C1    = V0_C * phi;
    C.C2    = V0_C * psi;
    C.C3    = V0_C * chi;

    // One-time double-precision Taylor coefficients for
    // G(u) = (1+u)*E(1+u)/beta, E(f) = 1 - exp(ln(1-beta)/f).
    {
        const double bd  = (double)beta;
        const double c   = log(1.0 - bd);
        const double omb = 1.0 - bd;
        double a[6], A[6], e[6];
        a[0] = 0.0;
        #pragma unroll
        for (int k = 1; k < 6; k++) a[k] = (k & 1) ? -c : c;
        A[0] = 1.0;
        #pragma unroll
        for (int k = 0; k < 5; k++) {
            double sum = 0.0;
            #pragma unroll
            for (int j = 0; j <= k; j++) sum += (double)(j + 1) * a[j + 1] * A[k - j];
            A[k + 1] = sum / (double)(k + 1);
        }
        e[0] = 1.0 - omb * A[0];
        #pragma unroll
        for (int k = 1; k < 6; k++) e[k] = -omb * A[k];
        const double ibd = 1.0 / bd;
        C.g0 = (float)(e[0] * ibd);
        C.g1 = (float)((e[1] + e[0]) * ibd);
        C.g2 = (float)((e[2] + e[1]) * ibd);
        C.g3 = (float)((e[3] + e[2]) * ibd);
        C.g4 = (float)((e[4] + e[3]) * ibd);
    }

    BWState st;
    st.s = 0.0f; st.f = 1.0f; st.v = 1.0f; st.q = 1.0f;
    st.G   = C.g0;                       // u = 0
    st.in1 = fmaf(-C.mu, 0.0f, -C.sigma * 0.0f);
    st.fv  = st.f - st.v;                // 0
    st.qd  = st.G - st.q;                // g0 - 1

    const float* np = noise + gid;
    float*       op = out   + gid;

    const int nch = T / U;

    float bufA[U], bufB[U];
    if (nch > 0) {
        #pragma unroll
        for (int i = 0; i < U; i++) bufA[i] = __ldcs(np + (size_t)i * BS);
    }

    int c = 0;
    for (; c + 1 < nch; c += 2) {
        {   // prefetch chunk c+1
            const float* pp = np + (size_t)(c + 1) * U * BS;
            #pragma unroll
            for (int i = 0; i < U; i++) bufB[i] = __ldcs(pp + (size_t)i * BS);
        }
        {   // compute chunk c
            float* o = op + (size_t)c * U * BS;
            #pragma unroll
            for (int i = 0; i < U; i++)
                __stcs(o + (size_t)i * BS, bw_step(st, C, bufA[i]));
        }
        if (c + 2 < nch) {   // prefetch chunk c+2
            const float* pp = np + (size_t)(c + 2) * U * BS;
            #pragma unroll
            for (int i = 0; i < U; i++) bufA[i] = __ldcs(pp + (size_t)i * BS);
        }
        {   // compute chunk c+1
            float* o = op + (size_t)(c + 1) * U * BS;
            #pragma unroll
            for (int i = 0; i < U; i++)
                __stcs(o + (size_t)i * BS, bw_step(st, C, bufB[i]));
        }
    }
    if (c < nch) {  // odd trailing chunk
        float* o = op + (size_t)c * U * BS;
        #pragma unroll
        for (int i = 0; i < U; i++)
            __stcs(o + (size_t)i * BS, bw_step(st, C, bufA[i]));
        c++;
    }

    // Tail (T not divisible by U).
    for (int t = nch * U; t < T; t++) {
        __stcs(op + (size_t)t * BS, bw_step(st, C, __ldcs(np + (size_t)t * BS)));
    }
}

extern "C" void kernel_launch(void* const* d_in, const int* in_sizes, int n_in,
                              void* d_out, int out_size)
{
    const float* noise = (const float*)d_in[0];
    const int T = in_sizes[0] / BATCH_C;

    const int threads = 128;
    // Pad grid past the low-grid issue-throttle threshold (>=148 CTAs).
    // Blocks 128..159 fail the gid guard and exit immediately; the 128
    // working blocks still land on distinct SMs in wave 1.
    const int blocks  = 160;

    bw_bold_kernel<20, BATCH_C><<<blocks, threads>>>(
        noise,
        (const float*)d_in[1], (const float*)d_in[2],
        (const float*)d_in[3], (const float*)d_in[4],
        (const float*)d_in[5], (const float*)d_in[6],
        (const float*)d_in[7],
        (float*)d_out, T);
}

// round 11
// speedup vs baseline: 1.0734x; 1.0734x over previous
#include <cuda_runtime.h>
#include <cuda_bf16.h>

// Balloon-Windkessel BOLD, explicit Euler, T=1000 steps, B=16384 sims.
// R11: warp-specialized split of each sim across an A-warp and a B-warp.
//  A (tid 0..127):  s,f recurrence + u=f-1 + Horner G(u); writes (f2,G)
//                   per step to shared memory (bit-exact float transport).
//  B (tid 128..255): v,q recurrences + BOLD readout + STG, consuming the
//                   (f,G) stream one chunk behind A (double-buffered smem,
//                   one __syncthreads per 20-step chunk).
// Why: R7-R10 proved the single warp/SMSP is dependency-stall bound
// (cyc/step invariant to op count). B caps warps at 512 = 1/SMSP; the split
// doubles warps to 2/SMSP (A on wid0-3, B on wid4-7 -> each SMSP gets one A
// + one B) so independent stalls interleave. All arithmetic ops, order and
// values identical to R9 -> output bit-identical (rel_err 1.140145e-4).

#define DT_C        0.01f
#define V0_C        0.02f
#define NOISE_AMP_C 0.01f
#define BATCH_C     16384

__device__ __forceinline__ float fast_rcp(float x) {
    float r; asm("rcp.approx.f32 %0, %1;" : "=f"(r) : "f"(x)); return r;
}

struct BWConst {
    float sigma, mu, c_vl;
    float C0, C1, C2, C3;        // readout constants
    float g0, g1, g2, g3, g4;    // G(u) Taylor coefficients (deg 4)
};

// ---- A-side step: update s,f; compute (f2, G(f2)); stage in1. ----
__device__ __forceinline__ float2 a_step(float& a_s, float& a_f, float& a_in1,
                                         const BWConst& C, float z)
{
    const float s2 = fmaf(DT_C, fmaf(NOISE_AMP_C, z, a_in1), a_s);
    const float f2 = fmaf(DT_C, a_s, a_f);
    const float u  = f2 - 1.0f;
    float p = fmaf(C.g4, u, C.g3);
    p       = fmaf(p,   u, C.g2);
    p       = fmaf(p,   u, C.g1);
    const float G = fmaf(p, u, C.g0);
    a_in1 = fmaf(-C.mu, u, -C.sigma * s2);
    a_s = s2; a_f = f2;
    return make_float2(f2, G);
}

// ---- B-side step: update v,q from staged fv,qd; restage; readout. ----
__device__ __forceinline__ float b_step(float& b_v, float& b_q,
                                        float& b_fv, float& b_qd,
                                        const BWConst& C, float2 fg)
{
    const float v2 = fmaf(C.c_vl, b_fv, b_v);
    const float q2 = fmaf(C.c_vl, b_qd, b_q);
    b_fv = fg.x - v2;
    b_qd = fg.y - q2;
    const float rv = fast_rcp(v2);
    const float t0 = fmaf(-C.C3, v2, C.C0);
    const float t1 = fmaf(-C.C1, q2, t0);
    const float y  = fmaf(-C.C2 * q2, rv, t1);
    b_v = v2; b_q = q2;
    return y;
}

template<int U, int BS>
__global__ __launch_bounds__(256, 1)
void bw_bold_kernel(const float* __restrict__ noise,
                    const float* __restrict__ sigma_p,
                    const float* __restrict__ mu_p,
                    const float* __restrict__ lamb_p,
                    const float* __restrict__ beta_p,
                    const float* __restrict__ psi_p,
                    const float* __restrict__ phi_p,
                    const float* __restrict__ chi_p,
                    float* __restrict__ out,
                    int T)
{
    __shared__ float2 s_fg[2][U][128];   // (f,G) stream, double-buffered

    const int tid  = threadIdx.x;
    const bool isA = (tid < 128);
    const int lane = tid & 127;
    const int sim  = blockIdx.x * 128 + lane;

    BWConst C;
    C.sigma = __ldg(sigma_p);
    C.mu    = __ldg(mu_p);
    const float lamb = __ldg(lamb_p);
    const float beta = __ldg(beta_p);
    const float psi  = __ldg(psi_p);
    const float phi  = __ldg(phi_p);
    const float chi  = __ldg(chi_p);
    C.c_vl  = DT_C / lamb;
    C.C0    = V0_C * (phi + psi + chi);
    C.C1    = V0_C * phi;
    C.C2    = V0_C * psi;
    C.C3    = V0_C * chi;

    // One-time double-precision Taylor coefficients for
    // G(u) = (1+u)*E(1+u)/beta, E(f) = 1 - exp(ln(1-beta)/f).
    {
        const double bd  = (double)beta;
        const double c   = log(1.0 - bd);
        const double omb = 1.0 - bd;
        double a[6], A[6], e[6];
        a[0] = 0.0;
        #pragma unroll
        for (int k = 1; k < 6; k++) a[k] = (k & 1) ? -c : c;
        A[0] = 1.0;
        #pragma unroll
        for (int k = 0; k < 5; k++) {
            double sum = 0.0;
            #pragma unroll
            for (int j = 0; j <= k; j++) sum += (double)(j + 1) * a[j + 1] * A[k - j];
            A[k + 1] = sum / (double)(k + 1);
        }
        e[0] = 1.0 - omb * A[0];
        #pragma unroll
        for (int k = 1; k < 6; k++) e[k] = -omb * A[k];
        const double ibd = 1.0 / bd;
        C.g0 = (float)(e[0] * ibd);
        C.g1 = (float)((e[1] + e[0]) * ibd);
        C.g2 = (float)((e[2] + e[1]) * ibd);
        C.g3 = (float)((e[3] + e[2]) * ibd);
        C.g4 = (float)((e[4] + e[3]) * ibd);
    }

    // Per-role state (registers exist in all threads; only one role uses each).
    float a_s = 0.0f, a_f = 1.0f;
    float a_in1 = fmaf(-C.mu, 0.0f, -C.sigma * 0.0f);
    float b_v = 1.0f, b_q = 1.0f;
    float b_fv = 0.0f;                 // f0 - v0
    float b_qd = C.g0 - 1.0f;          // G(f0) - q0

    const float* np = noise + sim;
    float*       op = out   + sim;

    const int nch = T / U;
    float nA[U], nB[U];

    // ---- Prologue: A loads noise chunks 0,1 and produces chunk 0. ----
    if (isA && nch > 0) {
        #pragma unroll
        for (int i = 0; i < U; i++) nA[i] = np[(size_t)i * BS];
        if (nch > 1) {
            #pragma unroll
            for (int i = 0; i < U; i++) nB[i] = np[(size_t)(U + i) * BS];
        }
        #pragma unroll
        for (int i = 0; i < U; i++)
            s_fg[0][i][lane] = a_step(a_s, a_f, a_in1, C, nA[i]);
    }
    __syncthreads();

    // ---- Pipelined main loop: A produces chunk c+1, B consumes chunk c. ----
    for (int c = 0; c < nch; c++) {
        if (isA) {
            if (c + 1 < nch) {
                const float* pp2 = np + (size_t)(c + 2) * U * BS;
                if ((c & 1) == 0) {
                    if (c + 2 < nch) {
                        #pragma unroll
                        for (int i = 0; i < U; i++) nA[i] = pp2[(size_t)i * BS];
                    }
                    #pragma unroll
                    for (int i = 0; i < U; i++)
                        s_fg[1][i][lane] = a_step(a_s, a_f, a_in1, C, nB[i]);
                } else {
                    if (c + 2 < nch) {
                        #pragma unroll
                        for (int i = 0; i < U; i++) nB[i] = pp2[(size_t)i * BS];
                    }
                    #pragma unroll
                    for (int i = 0; i < U; i++)
                        s_fg[0][i][lane] = a_step(a_s, a_f, a_in1, C, nA[i]);
                }
            }
        } else {
            const int b = c & 1;
            float2 fg[U];
            #pragma unroll
            for (int i = 0; i < U; i++) fg[i] = s_fg[b][i][lane];
            float* o = op + (size_t)c * U * BS;
            #pragma unroll
            for (int i = 0; i < U; i++)
                o[(size_t)i * BS] = b_step(b_v, b_q, b_fv, b_qd, C, fg[i]);
        }
        __syncthreads();
    }

    // ---- Tail (T not divisible by U). ----
    const int rem = T - nch * U;
    if (rem > 0) {
        if (isA) {
            const float* pp = np + (size_t)nch * U * BS;
            for (int i = 0; i < rem; i++)
                s_fg[nch & 1][i][lane] =
                    a_step(a_s, a_f, a_in1, C, pp[(size_t)i * BS]);
        }
        __syncthreads();
        if (!isA) {
            float* o = op + (size_t)nch * U * BS;
            for (int i = 0; i < rem; i++)
                o[(size_t)i * BS] =
                    b_step(b_v, b_q, b_fv, b_qd, C, s_fg[nch & 1][i][lane]);
        }
    }
}

extern "C" void kernel_launch(void* const* d_in, const int* in_sizes, int n_in,
                              void* d_out, int out_size)
{
    const float* noise = (const float*)d_in[0];
    const int T = in_sizes[0] / BATCH_C;

    // 128 blocks x 256 threads: 128 sims/block split across 4 A-warps +
    // 4 B-warps -> one A-warp AND one B-warp per SMSP (wid%4 pairing).
    const int threads = 256;
    const int blocks  = BATCH_C / 128;

    bw_bold_kernel<20, BATCH_C><<<blocks, threads>>>(
        noise,
        (const float*)d_in[1], (const float*)d_in[2],
        (const float*)d_in[3], (const float*)d_in[4],
        (const float*)d_in[5], (const float*)d_in[6],
        (const float*)d_in[7],
        (float*)d_out, T);
}